// round 5
// baseline (speedup 1.0000x reference)
#include <cuda_runtime.h>
#include <float.h>

#define BB 2
#define MM 4096
#define NN 16384
#define CC 256
#define KK 3
#define CH 8
#define CHM (MM / CH)   // 512 candidates per chunk

// Scratch (no cudaMalloc allowed)
__device__ float g_p1t[BB * MM * CC];       // p1 transposed: [b][m][o], o contiguous
__device__ int   g_idx[BB * NN * KK];
__device__ float g_wgt[BB * NN * KK];
__device__ float g_pd[BB * NN * CH * KK];   // partial knn distances (surrogate)
__device__ int   g_pi[BB * NN * CH * KK];   // partial knn indices

// ---------------------------------------------------------------------------
// kNN partial: 256 queries x one 512-candidate chunk per block.
// Surrogate distance d = |p|^2 - 2 q.p (|q|^2 added in merge).
// ---------------------------------------------------------------------------
__global__ void knn_part_kernel(const float* __restrict__ xyz1,
                                const float* __restrict__ xyz2) {
    __shared__ float4 s[CHM];
    const int b = blockIdx.z;
    const int c = blockIdx.y;
    const int mbase = c * CHM;
    for (int t = threadIdx.x; t < CHM; t += 256) {
        const float x = xyz1[(b * 3 + 0) * MM + mbase + t];
        const float y = xyz1[(b * 3 + 1) * MM + mbase + t];
        const float z = xyz1[(b * 3 + 2) * MM + mbase + t];
        s[t] = make_float4(x, y, z, fmaf(x, x, fmaf(y, y, z * z)));
    }
    __syncthreads();

    const int n = blockIdx.x * 256 + threadIdx.x;
    const float ax = -2.0f * xyz2[(b * 3 + 0) * NN + n];
    const float ay = -2.0f * xyz2[(b * 3 + 1) * NN + n];
    const float az = -2.0f * xyz2[(b * 3 + 2) * NN + n];

    float d0 = FLT_MAX, d1 = FLT_MAX, d2 = FLT_MAX;
    int   i0 = 0, i1 = 0, i2 = 0;

    #pragma unroll 4
    for (int m = 0; m < CHM; m++) {
        const float4 p = s[m];
        const float d = fmaf(p.x, ax, fmaf(p.y, ay, fmaf(p.z, az, p.w)));
        if (d < d2) {
            const int gi = mbase + m;
            if (d < d1) {
                if (d < d0) { d2 = d1; i2 = i1; d1 = d0; i1 = i0; d0 = d; i0 = gi; }
                else        { d2 = d1; i2 = i1; d1 = d;  i1 = gi; }
            } else          { d2 = d;  i2 = gi; }
        }
    }

    const int base = ((b * NN + n) * CH + c) * KK;
    g_pd[base + 0] = d0; g_pd[base + 1] = d1; g_pd[base + 2] = d2;
    g_pi[base + 0] = i0; g_pi[base + 1] = i1; g_pi[base + 2] = i2;
}

// ---------------------------------------------------------------------------
// kNN merge: merge 8 chunk-ordered top-3 partials; compute weights.
// ---------------------------------------------------------------------------
__global__ void knn_merge_kernel(const float* __restrict__ xyz2) {
    const int gid = blockIdx.x * 256 + threadIdx.x;   // 0 .. BB*NN-1
    const int b = gid / NN;
    const int n = gid - b * NN;

    const float qx = xyz2[(b * 3 + 0) * NN + n];
    const float qy = xyz2[(b * 3 + 1) * NN + n];
    const float qz = xyz2[(b * 3 + 2) * NN + n];
    const float qn = fmaf(qx, qx, fmaf(qy, qy, qz * qz));

    float d0 = FLT_MAX, d1 = FLT_MAX, d2 = FLT_MAX;
    int   i0 = 0, i1 = 0, i2 = 0;
    const int base = gid * CH * KK;
    #pragma unroll
    for (int t = 0; t < CH * KK; t++) {
        const float d = g_pd[base + t];
        if (d < d2) {
            const int gi = g_pi[base + t];
            if (d < d1) {
                if (d < d0) { d2 = d1; i2 = i1; d1 = d0; i1 = i0; d0 = d; i0 = gi; }
                else        { d2 = d1; i2 = i1; d1 = d;  i1 = gi; }
            } else          { d2 = d;  i2 = gi; }
        }
    }

    const float e0 = fmaxf(d0 + qn, 0.0f);
    const float e1 = fmaxf(d1 + qn, 0.0f);
    const float e2 = fmaxf(d2 + qn, 0.0f);
    const float r0 = 1.0f / (e0 + 1e-8f);
    const float r1 = 1.0f / (e1 + 1e-8f);
    const float r2 = 1.0f / (e2 + 1e-8f);
    const float sc = 1.0f / (r0 + r1 + r2);

    const int ob = gid * KK;
    g_idx[ob + 0] = i0; g_idx[ob + 1] = i1; g_idx[ob + 2] = i2;
    g_wgt[ob + 0] = r0 * sc; g_wgt[ob + 1] = r1 * sc; g_wgt[ob + 2] = r2 * sc;
}

// ---------------------------------------------------------------------------
// GEMM1: p1t[b][m][o] = sum_c w1[o][c]*points_1[b][c][m] + b1[o]
// 128(o) x 64(m) tile, 256 threads, 8x4 per thread (unchanged from R2).
// ---------------------------------------------------------------------------
__global__ __launch_bounds__(256) void gemm1_kernel(
        const float* __restrict__ w1, const float* __restrict__ b1,
        const float* __restrict__ p1in) {
    __shared__ float As[16][132];
    __shared__ float Bs[16][68];
    const int b  = blockIdx.z;
    const int m0 = blockIdx.x * 64;
    const int o0 = blockIdx.y * 128;
    const int tid = threadIdx.x;
    const int tx = tid & 15;
    const int ty = tid >> 4;

    float acc[8][4] = {};

    for (int kc = 0; kc < CC; kc += 16) {
        #pragma unroll
        for (int u = 0; u < 2; u++) {
            const int s = tid * 2 + u;
            const int o = s >> 2, kq = s & 3;
            const float4 w4 = *(const float4*)&w1[(o0 + o) * CC + kc + kq * 4];
            As[kq * 4 + 0][o] = w4.x; As[kq * 4 + 1][o] = w4.y;
            As[kq * 4 + 2][o] = w4.z; As[kq * 4 + 3][o] = w4.w;
        }
        {
            const int k = tid >> 4, n4 = tid & 15;
            const float4 b4 = *(const float4*)&p1in[(b * CC + kc + k) * MM + m0 + n4 * 4];
            *(float4*)&Bs[k][n4 * 4] = b4;
        }
        __syncthreads();
        #pragma unroll
        for (int k = 0; k < 16; k++) {
            const float4 a0 = *(const float4*)&As[k][ty * 8];
            const float4 a1 = *(const float4*)&As[k][ty * 8 + 4];
            const float4 bv = *(const float4*)&Bs[k][tx * 4];
            const float ar[8] = {a0.x, a0.y, a0.z, a0.w, a1.x, a1.y, a1.z, a1.w};
            const float br[4] = {bv.x, bv.y, bv.z, bv.w};
            #pragma unroll
            for (int i = 0; i < 8; i++)
                #pragma unroll
                for (int j = 0; j < 4; j++)
                    acc[i][j] = fmaf(ar[i], br[j], acc[i][j]);
        }
        __syncthreads();
    }

    const float4 bias0 = *(const float4*)&b1[o0 + ty * 8];
    const float4 bias1 = *(const float4*)&b1[o0 + ty * 8 + 4];
    const float bbv[8] = {bias0.x, bias0.y, bias0.z, bias0.w,
                          bias1.x, bias1.y, bias1.z, bias1.w};
    #pragma unroll
    for (int j = 0; j < 4; j++) {
        const int m = m0 + tx * 4 + j;
        float* dst = &g_p1t[((size_t)(b * MM + m)) * CC + o0 + ty * 8];
        float4 v0, v1;
        v0.x = acc[0][j] + bbv[0]; v0.y = acc[1][j] + bbv[1];
        v0.z = acc[2][j] + bbv[2]; v0.w = acc[3][j] + bbv[3];
        v1.x = acc[4][j] + bbv[4]; v1.y = acc[5][j] + bbv[5];
        v1.z = acc[6][j] + bbv[6]; v1.w = acc[7][j] + bbv[7];
        *(float4*)dst = v0;
        *(float4*)(dst + 4) = v1;
    }
}

// ---------------------------------------------------------------------------
// GEMM2 + fused 3-NN interpolation epilogue.
// 128(o) x 128(n) tile, 256 threads, 8x8 per thread, K-chunk 8,
// double-buffered smem (one sync per chunk).
// 64 FMA per 4 LDS.128 per thread -> smem demand ~50% at full FMA rate.
// ---------------------------------------------------------------------------
__global__ __launch_bounds__(256) void gemm2_kernel(
        const float* __restrict__ w2, const float* __restrict__ b2,
        const float* __restrict__ p2in, float* __restrict__ outp) {
    __shared__ float As[2][8][132];   // [buf][k][o]
    __shared__ float Bs[2][8][132];   // [buf][k][n]
    const int b  = blockIdx.z;
    const int n0 = blockIdx.x * 128;
    const int o0 = blockIdx.y * 128;
    const int tid = threadIdx.x;
    const int tx = tid & 15;          // n: 8 cols each
    const int ty = tid >> 4;          // o: 8 rows each

    // A-load mapping: 128 o x 8 k = 256 float4 (along c)
    const int a_o  = tid >> 1;        // 0..127
    const int a_kq = (tid & 1) * 4;   // 0 or 4
    // B-load mapping: 8 k x 128 n = 256 float4 (along n)
    const int b_k  = tid >> 5;        // 0..7
    const int b_n  = (tid & 31) * 4;  // 0..124

    const float* a_src = &w2[(o0 + a_o) * CC + a_kq];
    const float* b_src = &p2in[((size_t)(b * CC + b_k)) * NN + n0 + b_n];

    float acc[8][8] = {};

    // prefetch chunk 0
    float4 pa = *(const float4*)a_src;
    float4 pb = *(const float4*)b_src;
    As[0][a_kq + 0][a_o] = pa.x; As[0][a_kq + 1][a_o] = pa.y;
    As[0][a_kq + 2][a_o] = pa.z; As[0][a_kq + 3][a_o] = pa.w;
    *(float4*)&Bs[0][b_k][b_n] = pb;
    __syncthreads();

    #pragma unroll 1
    for (int kc = 0; kc < 32; kc++) {
        const int buf = kc & 1;
        if (kc + 1 < 32) {
            pa = *(const float4*)(a_src + (kc + 1) * 8);
            pb = *(const float4*)(b_src + (size_t)(kc + 1) * 8 * NN);
        }
        #pragma unroll
        for (int k = 0; k < 8; k++) {
            const float4 a0 = *(const float4*)&As[buf][k][ty * 8];
            const float4 a1 = *(const float4*)&As[buf][k][ty * 8 + 4];
            const float4 b0 = *(const float4*)&Bs[buf][k][tx * 8];
            const float4 b1 = *(const float4*)&Bs[buf][k][tx * 8 + 4];
            const float ar[8] = {a0.x, a0.y, a0.z, a0.w, a1.x, a1.y, a1.z, a1.w};
            const float br[8] = {b0.x, b0.y, b0.z, b0.w, b1.x, b1.y, b1.z, b1.w};
            #pragma unroll
            for (int i = 0; i < 8; i++)
                #pragma unroll
                for (int j = 0; j < 8; j++)
                    acc[i][j] = fmaf(ar[i], br[j], acc[i][j]);
        }
        if (kc + 1 < 32) {
            const int nb = buf ^ 1;
            As[nb][a_kq + 0][a_o] = pa.x; As[nb][a_kq + 1][a_o] = pa.y;
            As[nb][a_kq + 2][a_o] = pa.z; As[nb][a_kq + 3][a_o] = pa.w;
            *(float4*)&Bs[nb][b_k][b_n] = pb;
            __syncthreads();
        }
    }

    // Epilogue: 3-NN weighted gather from p1t (L2-resident, o-contiguous)
    #pragma unroll
    for (int j = 0; j < 8; j++) {
        const int n = n0 + tx * 8 + j;
        const int kb = (b * NN + n) * KK;
        const int ia = g_idx[kb + 0];
        const int ib = g_idx[kb + 1];
        const int ic = g_idx[kb + 2];
        const float wa = g_wgt[kb + 0];
        const float wb = g_wgt[kb + 1];
        const float wc = g_wgt[kb + 2];
        const float* pA = &g_p1t[((size_t)(b * MM + ia)) * CC + o0 + ty * 8];
        const float* pB = &g_p1t[((size_t)(b * MM + ib)) * CC + o0 + ty * 8];
        const float* pC = &g_p1t[((size_t)(b * MM + ic)) * CC + o0 + ty * 8];
        const float4 va0 = *(const float4*)pA, va1 = *(const float4*)(pA + 4);
        const float4 vb0 = *(const float4*)pB, vb1 = *(const float4*)(pB + 4);
        const float4 vc0 = *(const float4*)pC, vc1 = *(const float4*)(pC + 4);
        acc[0][j] += wa * va0.x + wb * vb0.x + wc * vc0.x;
        acc[1][j] += wa * va0.y + wb * vb0.y + wc * vc0.y;
        acc[2][j] += wa * va0.z + wb * vb0.z + wc * vc0.z;
        acc[3][j] += wa * va0.w + wb * vb0.w + wc * vc0.w;
        acc[4][j] += wa * va1.x + wb * vb1.x + wc * vc1.x;
        acc[5][j] += wa * va1.y + wb * vb1.y + wc * vc1.y;
        acc[6][j] += wa * va1.z + wb * vb1.z + wc * vc1.z;
        acc[7][j] += wa * va1.w + wb * vb1.w + wc * vc1.w;
    }

    const float4 bias0 = *(const float4*)&b2[o0 + ty * 8];
    const float4 bias1 = *(const float4*)&b2[o0 + ty * 8 + 4];
    const float bbv[8] = {bias0.x, bias0.y, bias0.z, bias0.w,
                          bias1.x, bias1.y, bias1.z, bias1.w};
    #pragma unroll
    for (int i = 0; i < 8; i++) {
        const int o = o0 + ty * 8 + i;
        float* dst = &outp[((size_t)(b * CC + o)) * NN + n0 + tx * 8];
        float4 v0, v1;
        v0.x = acc[i][0] + bbv[i]; v0.y = acc[i][1] + bbv[i];
        v0.z = acc[i][2] + bbv[i]; v0.w = acc[i][3] + bbv[i];
        v1.x = acc[i][4] + bbv[i]; v1.y = acc[i][5] + bbv[i];
        v1.z = acc[i][6] + bbv[i]; v1.w = acc[i][7] + bbv[i];
        *(float4*)dst = v0;
        *(float4*)(dst + 4) = v1;
    }
}

extern "C" void kernel_launch(void* const* d_in, const int* in_sizes, int n_in,
                              void* d_out, int out_size) {
    const float* xyz1 = (const float*)d_in[0];
    const float* xyz2 = (const float*)d_in[1];
    const float* p1   = (const float*)d_in[2];
    const float* p2   = (const float*)d_in[3];
    const float* w1   = (const float*)d_in[4];
    const float* b1   = (const float*)d_in[5];
    const float* w2   = (const float*)d_in[6];
    const float* b2   = (const float*)d_in[7];
    float* out = (float*)d_out;

    // Output = (xyz_2, interpolated + p2) flattened
    cudaMemcpyAsync(out, xyz2, (size_t)BB * 3 * NN * sizeof(float),
                    cudaMemcpyDeviceToDevice);

    knn_part_kernel<<<dim3(NN / 256, CH, BB), 256>>>(xyz1, xyz2);
    knn_merge_kernel<<<(BB * NN) / 256, 256>>>(xyz2);
    gemm1_kernel<<<dim3(MM / 64, CC / 128, BB), 256>>>(w1, b1, p1);
    gemm2_kernel<<<dim3(NN / 128, CC / 128, BB), 256>>>(w2, b2, p2,
                                                        out + (size_t)BB * 3 * NN);
}

// round 11
// speedup vs baseline: 1.0682x; 1.0682x over previous
#include <cuda_runtime.h>
#include <float.h>
#include <cstdint>

#define BB 2
#define MM 4096
#define NN 16384
#define CC 256
#define KK 3
#define CH 16
#define CHM (MM / CH)   // 256 candidates per chunk

// Scratch (no cudaMalloc allowed)
__device__ float g_p1t[BB * MM * CC];       // p1 transposed: [b][m][o], o contiguous
__device__ int   g_idx[BB * NN * KK];
__device__ float g_wgt[BB * NN * KK];
__device__ float g_pd[BB * NN * CH * KK];
__device__ int   g_pi[BB * NN * CH * KK];

// ---------------------------------------------------------------------------
// kNN partial: 256 queries x one 256-candidate chunk per block.
// Surrogate distance d = |p|^2 - 2 q.p (|q|^2 added in merge).
// ---------------------------------------------------------------------------
__global__ void knn_part_kernel(const float* __restrict__ xyz1,
                                const float* __restrict__ xyz2) {
    __shared__ float4 s[CHM];
    const int b = blockIdx.z;
    const int c = blockIdx.y;
    const int mbase = c * CHM;
    for (int t = threadIdx.x; t < CHM; t += 256) {
        const float x = xyz1[(b * 3 + 0) * MM + mbase + t];
        const float y = xyz1[(b * 3 + 1) * MM + mbase + t];
        const float z = xyz1[(b * 3 + 2) * MM + mbase + t];
        s[t] = make_float4(x, y, z, fmaf(x, x, fmaf(y, y, z * z)));
    }
    __syncthreads();

    const int n = blockIdx.x * 256 + threadIdx.x;
    const float ax = -2.0f * xyz2[(b * 3 + 0) * NN + n];
    const float ay = -2.0f * xyz2[(b * 3 + 1) * NN + n];
    const float az = -2.0f * xyz2[(b * 3 + 2) * NN + n];

    float d0 = FLT_MAX, d1 = FLT_MAX, d2 = FLT_MAX;
    int   i0 = 0, i1 = 0, i2 = 0;

    #pragma unroll 4
    for (int m = 0; m < CHM; m++) {
        const float4 p = s[m];
        const float d = fmaf(p.x, ax, fmaf(p.y, ay, fmaf(p.z, az, p.w)));
        if (d < d2) {
            const int gi = mbase + m;
            if (d < d1) {
                if (d < d0) { d2 = d1; i2 = i1; d1 = d0; i1 = i0; d0 = d; i0 = gi; }
                else        { d2 = d1; i2 = i1; d1 = d;  i1 = gi; }
            } else          { d2 = d;  i2 = gi; }
        }
    }

    const int base = ((b * NN + n) * CH + c) * KK;
    g_pd[base + 0] = d0; g_pd[base + 1] = d1; g_pd[base + 2] = d2;
    g_pi[base + 0] = i0; g_pi[base + 1] = i1; g_pi[base + 2] = i2;
}

// ---------------------------------------------------------------------------
// kNN merge: merge 16 chunk-ordered top-3 partials; compute weights.
// ---------------------------------------------------------------------------
__global__ void knn_merge_kernel(const float* __restrict__ xyz2) {
    const int gid = blockIdx.x * 256 + threadIdx.x;
    const int b = gid / NN;
    const int n = gid - b * NN;

    const float qx = xyz2[(b * 3 + 0) * NN + n];
    const float qy = xyz2[(b * 3 + 1) * NN + n];
    const float qz = xyz2[(b * 3 + 2) * NN + n];
    const float qn = fmaf(qx, qx, fmaf(qy, qy, qz * qz));

    float d0 = FLT_MAX, d1 = FLT_MAX, d2 = FLT_MAX;
    int   i0 = 0, i1 = 0, i2 = 0;
    const int base = gid * CH * KK;
    #pragma unroll
    for (int t = 0; t < CH * KK; t++) {
        const float d = g_pd[base + t];
        if (d < d2) {
            const int gi = g_pi[base + t];
            if (d < d1) {
                if (d < d0) { d2 = d1; i2 = i1; d1 = d0; i1 = i0; d0 = d; i0 = gi; }
                else        { d2 = d1; i2 = i1; d1 = d;  i1 = gi; }
            } else          { d2 = d;  i2 = gi; }
        }
    }

    const float e0 = fmaxf(d0 + qn, 0.0f);
    const float e1 = fmaxf(d1 + qn, 0.0f);
    const float e2 = fmaxf(d2 + qn, 0.0f);
    const float r0 = 1.0f / (e0 + 1e-8f);
    const float r1 = 1.0f / (e1 + 1e-8f);
    const float r2 = 1.0f / (e2 + 1e-8f);
    const float sc = 1.0f / (r0 + r1 + r2);

    const int ob = gid * KK;
    g_idx[ob + 0] = i0; g_idx[ob + 1] = i1; g_idx[ob + 2] = i2;
    g_wgt[ob + 0] = r0 * sc; g_wgt[ob + 1] = r1 * sc; g_wgt[ob + 2] = r2 * sc;
}

// ---------------------------------------------------------------------------
// FFMA GEMM engine with warp-uniform A-fragments.
// Block tile: 128(o) x 128(x). 8 warps; warp w owns o-rows [w*16, w*16+16)
// across all 128 x. Thread (lane l) owns 16(o) x 4(n=l*4..) outputs.
// A-fragment (16 floats per k) is warp-uniform -> LDS broadcast (1 wf per
// LDS.128); B-fragment is 1 conflict-free LDS.128 per lane. Crossbar demand
// ~= 8 wf per 64 FMA-cycles per warp (~50% of 128B/cyc at 2 FFMA/SMSP/cyc).
// K-chunks of 8, double-buffered, one __syncthreads per chunk.
// WHICH==1: x = m over points_1 -> writes g_p1t[b][m][o] + b1.
// WHICH==2: x = n over points_2 -> writes out[b][o][n] + b2 + 3-NN gather.
// ---------------------------------------------------------------------------
template <int WHICH>
__global__ __launch_bounds__(256, 2) void gemm_ffma(
        const float* __restrict__ W, const float* __restrict__ bias_v,
        const float* __restrict__ P, float* __restrict__ outp) {
    __shared__ float As[2][8][128];   // [buf][k][o]
    __shared__ float Bs[2][8][128];   // [buf][k][x]

    const int b  = blockIdx.z;
    const int x0 = blockIdx.x * 128;
    const int o0 = blockIdx.y * 128;
    const int tid  = threadIdx.x;
    const int warp = tid >> 5;
    const int lane = tid & 31;
    const size_t XDIM = (WHICH == 1) ? MM : NN;

    // A-load mapping: row = tid>>1 (o: 0..127), kq = (tid&1)*4 (k: 0..7 via 2 f4)
    const int a_row = tid >> 1;
    const int a_kq  = (tid & 1) * 4;
    // B-load mapping: bk = tid>>5 (k: 0..7), bn = (tid&31)*4
    const int b_k = tid >> 5;
    const int b_n = (tid & 31) * 4;

    const float* a_src = &W[(o0 + a_row) * CC + a_kq];
    const float* b_src = &P[((size_t)(b * CC) + b_k) * XDIM + x0 + b_n];

    float acc[16][4] = {};            // [o][x]

    // prefetch chunk 0
    float4 pa = *(const float4*)a_src;
    float4 pb = *(const float4*)b_src;
    As[0][a_kq + 0][a_row] = pa.x; As[0][a_kq + 1][a_row] = pa.y;
    As[0][a_kq + 2][a_row] = pa.z; As[0][a_kq + 3][a_row] = pa.w;
    *(float4*)&Bs[0][b_k][b_n] = pb;
    __syncthreads();

    const int ob = warp * 16;

    #pragma unroll 1
    for (int kc = 0; kc < 32; kc++) {
        const int buf = kc & 1;
        if (kc + 1 < 32) {
            pa = *(const float4*)(a_src + (kc + 1) * 8);
            pb = *(const float4*)(b_src + (size_t)(kc + 1) * 8 * XDIM);
        }
        #pragma unroll
        for (int k = 0; k < 8; k++) {
            // warp-uniform A (broadcast)
            const float4 a0 = *(const float4*)&As[buf][k][ob + 0];
            const float4 a1 = *(const float4*)&As[buf][k][ob + 4];
            const float4 a2 = *(const float4*)&As[buf][k][ob + 8];
            const float4 a3 = *(const float4*)&As[buf][k][ob + 12];
            const float4 bf = *(const float4*)&Bs[buf][k][lane * 4];
            const float ar[16] = {a0.x, a0.y, a0.z, a0.w, a1.x, a1.y, a1.z, a1.w,
                                  a2.x, a2.y, a2.z, a2.w, a3.x, a3.y, a3.z, a3.w};
            const float br[4] = {bf.x, bf.y, bf.z, bf.w};
            #pragma unroll
            for (int i = 0; i < 16; i++)
                #pragma unroll
                for (int j = 0; j < 4; j++)
                    acc[i][j] = fmaf(ar[i], br[j], acc[i][j]);
        }
        if (kc + 1 < 32) {
            const int nb = buf ^ 1;
            As[nb][a_kq + 0][a_row] = pa.x; As[nb][a_kq + 1][a_row] = pa.y;
            As[nb][a_kq + 2][a_row] = pa.z; As[nb][a_kq + 3][a_row] = pa.w;
            *(float4*)&Bs[nb][b_k][b_n] = pb;
            __syncthreads();
        }
    }

    const int o_base = o0 + ob;
    float bv[16];
    #pragma unroll
    for (int g = 0; g < 4; g++)
        *(float4*)&bv[g * 4] = *(const float4*)&bias_v[o_base + g * 4];

    if (WHICH == 1) {
        // p1t[b][m][o] = acc + b1[o]; per m, 4 float4 (o contiguous)
        #pragma unroll
        for (int j = 0; j < 4; j++) {
            const int m = x0 + lane * 4 + j;
            float* dst = &g_p1t[((size_t)(b * MM + m)) * CC + o_base];
            #pragma unroll
            for (int g = 0; g < 4; g++) {
                float4 v;
                v.x = acc[g * 4 + 0][j] + bv[g * 4 + 0];
                v.y = acc[g * 4 + 1][j] + bv[g * 4 + 1];
                v.z = acc[g * 4 + 2][j] + bv[g * 4 + 2];
                v.w = acc[g * 4 + 3][j] + bv[g * 4 + 3];
                *(float4*)(dst + g * 4) = v;
            }
        }
    } else {
        // 3-NN weighted gather from p1t (L2-resident, o-contiguous)
        #pragma unroll
        for (int j = 0; j < 4; j++) {
            const int n = x0 + lane * 4 + j;
            const int kb3 = (b * NN + n) * KK;
            const int ia = g_idx[kb3 + 0];
            const int ib = g_idx[kb3 + 1];
            const int ic = g_idx[kb3 + 2];
            const float wa = g_wgt[kb3 + 0];
            const float wb = g_wgt[kb3 + 1];
            const float wc = g_wgt[kb3 + 2];
            const float* pA = &g_p1t[((size_t)(b * MM + ia)) * CC + o_base];
            const float* pB = &g_p1t[((size_t)(b * MM + ib)) * CC + o_base];
            const float* pC = &g_p1t[((size_t)(b * MM + ic)) * CC + o_base];
            #pragma unroll
            for (int g = 0; g < 4; g++) {
                const float4 va = *(const float4*)(pA + g * 4);
                const float4 vb = *(const float4*)(pB + g * 4);
                const float4 vc = *(const float4*)(pC + g * 4);
                acc[g * 4 + 0][j] += wa * va.x + wb * vb.x + wc * vc.x;
                acc[g * 4 + 1][j] += wa * va.y + wb * vb.y + wc * vc.y;
                acc[g * 4 + 2][j] += wa * va.z + wb * vb.z + wc * vc.z;
                acc[g * 4 + 3][j] += wa * va.w + wb * vb.w + wc * vc.w;
            }
        }
        // out[b][o][n]: per o, one float4 across this thread's 4 n (coalesced)
        #pragma unroll
        for (int i = 0; i < 16; i++) {
            const int o = o_base + i;
            float4 v;
            v.x = acc[i][0] + bv[i];
            v.y = acc[i][1] + bv[i];
            v.z = acc[i][2] + bv[i];
            v.w = acc[i][3] + bv[i];
            *(float4*)&outp[((size_t)(b * CC + o)) * NN + x0 + lane * 4] = v;
        }
    }
}

extern "C" void kernel_launch(void* const* d_in, const int* in_sizes, int n_in,
                              void* d_out, int out_size) {
    const float* xyz1 = (const float*)d_in[0];
    const float* xyz2 = (const float*)d_in[1];
    const float* p1   = (const float*)d_in[2];
    const float* p2   = (const float*)d_in[3];
    const float* w1   = (const float*)d_in[4];
    const float* b1   = (const float*)d_in[5];
    const float* w2   = (const float*)d_in[6];
    const float* b2   = (const float*)d_in[7];
    float* out = (float*)d_out;

    // Output = (xyz_2, interpolated + p2) flattened
    cudaMemcpyAsync(out, xyz2, (size_t)BB * 3 * NN * sizeof(float),
                    cudaMemcpyDeviceToDevice);

    knn_part_kernel<<<dim3(NN / 256, CH, BB), 256>>>(xyz1, xyz2);
    knn_merge_kernel<<<(BB * NN) / 256, 256>>>(xyz2);
    gemm_ffma<1><<<dim3(MM / 128, CC / 128, BB), 256>>>(w1, b1, p1, nullptr);
    gemm_ffma<2><<<dim3(NN / 128, CC / 128, BB), 256>>>(w2, b2, p2,
                                                        out + (size_t)BB * 3 * NN);
}

// round 14
// speedup vs baseline: 1.0869x; 1.0175x over previous
#include <cuda_runtime.h>
#include <float.h>
#include <cstdint>

#define BB 2
#define MM 4096
#define NN 16384
#define CC 256
#define KK 3
#define CH 16
#define CHM (MM / CH)   // 256 candidates per chunk

// Scratch (no cudaMalloc allowed)
__device__ float g_p1t[BB * MM * CC];       // p1 transposed: [b][m][o], o contiguous
__device__ int   g_idx[BB * NN * KK];
__device__ float g_wgt[BB * NN * KK];
__device__ float g_pd[BB * NN * CH * KK];
__device__ int   g_pi[BB * NN * CH * KK];

__device__ __forceinline__ void cp_async16(uint32_t dst, const void* src) {
    asm volatile("cp.async.cg.shared.global [%0], [%1], 16;" :: "r"(dst), "l"(src));
}
#define CP_COMMIT() asm volatile("cp.async.commit_group;" ::: "memory")
#define CP_WAIT0()  asm volatile("cp.async.wait_group 0;" ::: "memory")

// ---------------------------------------------------------------------------
// kNN partial: 256 queries x one 256-candidate chunk per block.
// Surrogate distance d = |p|^2 - 2 q.p (|q|^2 added in merge).
// ---------------------------------------------------------------------------
__global__ void knn_part_kernel(const float* __restrict__ xyz1,
                                const float* __restrict__ xyz2) {
    __shared__ float4 s[CHM];
    const int b = blockIdx.z;
    const int c = blockIdx.y;
    const int mbase = c * CHM;
    for (int t = threadIdx.x; t < CHM; t += 256) {
        const float x = xyz1[(b * 3 + 0) * MM + mbase + t];
        const float y = xyz1[(b * 3 + 1) * MM + mbase + t];
        const float z = xyz1[(b * 3 + 2) * MM + mbase + t];
        s[t] = make_float4(x, y, z, fmaf(x, x, fmaf(y, y, z * z)));
    }
    __syncthreads();

    const int n = blockIdx.x * 256 + threadIdx.x;
    const float ax = -2.0f * xyz2[(b * 3 + 0) * NN + n];
    const float ay = -2.0f * xyz2[(b * 3 + 1) * NN + n];
    const float az = -2.0f * xyz2[(b * 3 + 2) * NN + n];

    float d0 = FLT_MAX, d1 = FLT_MAX, d2 = FLT_MAX;
    int   i0 = 0, i1 = 0, i2 = 0;

    #pragma unroll 4
    for (int m = 0; m < CHM; m++) {
        const float4 p = s[m];
        const float d = fmaf(p.x, ax, fmaf(p.y, ay, fmaf(p.z, az, p.w)));
        if (d < d2) {
            const int gi = mbase + m;
            if (d < d1) {
                if (d < d0) { d2 = d1; i2 = i1; d1 = d0; i1 = i0; d0 = d; i0 = gi; }
                else        { d2 = d1; i2 = i1; d1 = d;  i1 = gi; }
            } else          { d2 = d;  i2 = gi; }
        }
    }

    const int base = ((b * NN + n) * CH + c) * KK;
    g_pd[base + 0] = d0; g_pd[base + 1] = d1; g_pd[base + 2] = d2;
    g_pi[base + 0] = i0; g_pi[base + 1] = i1; g_pi[base + 2] = i2;
}

// ---------------------------------------------------------------------------
// kNN merge: merge 16 chunk-ordered top-3 partials; compute weights.
// ---------------------------------------------------------------------------
__global__ void knn_merge_kernel(const float* __restrict__ xyz2) {
    const int gid = blockIdx.x * 256 + threadIdx.x;
    const int b = gid / NN;
    const int n = gid - b * NN;

    const float qx = xyz2[(b * 3 + 0) * NN + n];
    const float qy = xyz2[(b * 3 + 1) * NN + n];
    const float qz = xyz2[(b * 3 + 2) * NN + n];
    const float qn = fmaf(qx, qx, fmaf(qy, qy, qz * qz));

    float d0 = FLT_MAX, d1 = FLT_MAX, d2 = FLT_MAX;
    int   i0 = 0, i1 = 0, i2 = 0;
    const int base = gid * CH * KK;
    #pragma unroll
    for (int t = 0; t < CH * KK; t++) {
        const float d = g_pd[base + t];
        if (d < d2) {
            const int gi = g_pi[base + t];
            if (d < d1) {
                if (d < d0) { d2 = d1; i2 = i1; d1 = d0; i1 = i0; d0 = d; i0 = gi; }
                else        { d2 = d1; i2 = i1; d1 = d;  i1 = gi; }
            } else          { d2 = d;  i2 = gi; }
        }
    }

    const float e0 = fmaxf(d0 + qn, 0.0f);
    const float e1 = fmaxf(d1 + qn, 0.0f);
    const float e2 = fmaxf(d2 + qn, 0.0f);
    const float r0 = 1.0f / (e0 + 1e-8f);
    const float r1 = 1.0f / (e1 + 1e-8f);
    const float r2 = 1.0f / (e2 + 1e-8f);
    const float sc = 1.0f / (r0 + r1 + r2);

    const int ob = gid * KK;
    g_idx[ob + 0] = i0; g_idx[ob + 1] = i1; g_idx[ob + 2] = i2;
    g_wgt[ob + 0] = r0 * sc; g_wgt[ob + 1] = r1 * sc; g_wgt[ob + 2] = r2 * sc;
}

// ---------------------------------------------------------------------------
// FFMA GEMM engine, warp-uniform A-fragments, templated o-tile.
// Block tile: OT(o) x 128(x), 8 warps. Warp w owns o-rows [w*RPW, (w+1)*RPW);
// lane l owns x-cols [l*4, l*4+4). A-fragment per k is warp-uniform (LDS
// broadcast); B-fragment is one conflict-free LDS.128 per lane.
// K-chunks of 16, double-buffered: B streamed via cp.async.cg (no reg
// round-trip); A (transposed) via LDG->STS. One __syncthreads per chunk.
// WHICH==1: x = m over points_1 -> writes g_p1t[b][m][o] + b1.
// WHICH==2: x = n over points_2 -> writes out[b][o][n] + b2 + 3-NN gather.
// ---------------------------------------------------------------------------
template <int WHICH, int OT>
__global__ __launch_bounds__(256, 2) void gemm_ffma(
        const float* __restrict__ W, const float* __restrict__ bias_v,
        const float* __restrict__ P, float* __restrict__ outp) {
    constexpr int RPW  = OT / 8;        // o-rows per warp (8 or 16)
    constexpr int NF4A = OT / 64;       // A float4 loads per thread per chunk
    constexpr int NCH  = CC / 16;       // 16 k-chunks

    __shared__ float As[2][16][OT];
    __shared__ float Bs[2][16][128];

    const int b  = blockIdx.z;
    const int x0 = blockIdx.x * 128;
    const int o0 = blockIdx.y * OT;
    const int tid  = threadIdx.x;
    const int warp = tid >> 5;
    const int lane = tid & 31;
    const size_t XDIM = (WHICH == 1) ? MM : NN;

    const uint32_t bsBase = (uint32_t)__cvta_generic_to_shared(&Bs[0][0][0]);

    // A-load mapping: f4 id -> row = id>>2 (o), q = (id&3)*4 (k-quad)
    int a_row[NF4A], a_q[NF4A];
    #pragma unroll
    for (int i = 0; i < NF4A; i++) {
        const int id = tid * NF4A + i;
        a_row[i] = id >> 2;
        a_q[i]   = (id & 3) * 4;
    }
    // B cp.async mapping: 2 x 16B per thread per chunk
    const int b_row0 = tid >> 5,          b_col0 = (tid & 31) * 4;
    const int b_row1 = (tid + 256) >> 5,  b_col1 = b_col0;

    float acc[RPW][4] = {};
    float4 pa[NF4A];

    // ---- chunk 0 ----
    #pragma unroll
    for (int i = 0; i < NF4A; i++)
        pa[i] = *(const float4*)&W[(o0 + a_row[i]) * CC + a_q[i]];
    cp_async16(bsBase + (uint32_t)((0 * 16 + b_row0) * 128 + b_col0) * 4,
               &P[((size_t)(b * CC) + b_row0) * XDIM + x0 + b_col0]);
    cp_async16(bsBase + (uint32_t)((0 * 16 + b_row1) * 128 + b_col1) * 4,
               &P[((size_t)(b * CC) + b_row1) * XDIM + x0 + b_col1]);
    CP_COMMIT();
    #pragma unroll
    for (int i = 0; i < NF4A; i++) {
        As[0][a_q[i] + 0][a_row[i]] = pa[i].x;
        As[0][a_q[i] + 1][a_row[i]] = pa[i].y;
        As[0][a_q[i] + 2][a_row[i]] = pa[i].z;
        As[0][a_q[i] + 3][a_row[i]] = pa[i].w;
    }
    CP_WAIT0();
    __syncthreads();

    const int ob = warp * RPW;

    #pragma unroll 1
    for (int kc = 0; kc < NCH; kc++) {
        const int buf = kc & 1;
        if (kc + 1 < NCH) {
            const int kb = (kc + 1) * 16;
            #pragma unroll
            for (int i = 0; i < NF4A; i++)
                pa[i] = *(const float4*)&W[(o0 + a_row[i]) * CC + kb + a_q[i]];
            const uint32_t sb = bsBase + (uint32_t)((buf ^ 1) * 16 * 128) * 4;
            cp_async16(sb + (uint32_t)(b_row0 * 128 + b_col0) * 4,
                       &P[((size_t)(b * CC) + kb + b_row0) * XDIM + x0 + b_col0]);
            cp_async16(sb + (uint32_t)(b_row1 * 128 + b_col1) * 4,
                       &P[((size_t)(b * CC) + kb + b_row1) * XDIM + x0 + b_col1]);
            CP_COMMIT();
        }
        #pragma unroll
        for (int k = 0; k < 16; k++) {
            float ar[RPW];
            #pragma unroll
            for (int g = 0; g < RPW / 4; g++)
                *(float4*)&ar[g * 4] = *(const float4*)&As[buf][k][ob + g * 4];
            const float4 bf = *(const float4*)&Bs[buf][k][lane * 4];
            const float br[4] = {bf.x, bf.y, bf.z, bf.w};
            #pragma unroll
            for (int i = 0; i < RPW; i++)
                #pragma unroll
                for (int j = 0; j < 4; j++)
                    acc[i][j] = fmaf(ar[i], br[j], acc[i][j]);
        }
        if (kc + 1 < NCH) {
            const int nb = buf ^ 1;
            #pragma unroll
            for (int i = 0; i < NF4A; i++) {
                As[nb][a_q[i] + 0][a_row[i]] = pa[i].x;
                As[nb][a_q[i] + 1][a_row[i]] = pa[i].y;
                As[nb][a_q[i] + 2][a_row[i]] = pa[i].z;
                As[nb][a_q[i] + 3][a_row[i]] = pa[i].w;
            }
            CP_WAIT0();
            __syncthreads();
        }
    }

    const int o_base = o0 + ob;
    float bv[RPW];
    #pragma unroll
    for (int g = 0; g < RPW / 4; g++)
        *(float4*)&bv[g * 4] = *(const float4*)&bias_v[o_base + g * 4];

    if (WHICH == 1) {
        // p1t[b][m][o] = acc + b1[o]; per m, RPW/4 float4 (o contiguous)
        #pragma unroll
        for (int j = 0; j < 4; j++) {
            const int m = x0 + lane * 4 + j;
            float* dst = &g_p1t[((size_t)(b * MM + m)) * CC + o_base];
            #pragma unroll
            for (int g = 0; g < RPW / 4; g++) {
                float4 v;
                v.x = acc[g * 4 + 0][j] + bv[g * 4 + 0];
                v.y = acc[g * 4 + 1][j] + bv[g * 4 + 1];
                v.z = acc[g * 4 + 2][j] + bv[g * 4 + 2];
                v.w = acc[g * 4 + 3][j] + bv[g * 4 + 3];
                *(float4*)(dst + g * 4) = v;
            }
        }
    } else {
        // 3-NN weighted gather from p1t (L2-resident, o-contiguous)
        #pragma unroll
        for (int j = 0; j < 4; j++) {
            const int n = x0 + lane * 4 + j;
            const int kb3 = (b * NN + n) * KK;
            const int ia = g_idx[kb3 + 0];
            const int ib = g_idx[kb3 + 1];
            const int ic = g_idx[kb3 + 2];
            const float wa = g_wgt[kb3 + 0];
            const float wb = g_wgt[kb3 + 1];
            const float wc = g_wgt[kb3 + 2];
            const float* pA = &g_p1t[((size_t)(b * MM + ia)) * CC + o_base];
            const float* pB = &g_p1t[((size_t)(b * MM + ib)) * CC + o_base];
            const float* pC = &g_p1t[((size_t)(b * MM + ic)) * CC + o_base];
            #pragma unroll
            for (int g = 0; g < RPW / 4; g++) {
                const float4 va = *(const float4*)(pA + g * 4);
                const float4 vb = *(const float4*)(pB + g * 4);
                const float4 vc = *(const float4*)(pC + g * 4);
                acc[g * 4 + 0][j] += wa * va.x + wb * vb.x + wc * vc.x;
                acc[g * 4 + 1][j] += wa * va.y + wb * vb.y + wc * vc.y;
                acc[g * 4 + 2][j] += wa * va.z + wb * vb.z + wc * vc.z;
                acc[g * 4 + 3][j] += wa * va.w + wb * vb.w + wc * vc.w;
            }
        }
        // out[b][o][n]: per o, one float4 across this thread's 4 n (coalesced)
        #pragma unroll
        for (int i = 0; i < RPW; i++) {
            const int o = o_base + i;
            float4 v;
            v.x = acc[i][0] + bv[i];
            v.y = acc[i][1] + bv[i];
            v.z = acc[i][2] + bv[i];
            v.w = acc[i][3] + bv[i];
            *(float4*)&outp[((size_t)(b * CC + o)) * NN + x0 + lane * 4] = v;
        }
    }
}

extern "C" void kernel_launch(void* const* d_in, const int* in_sizes, int n_in,
                              void* d_out, int out_size) {
    const float* xyz1 = (const float*)d_in[0];
    const float* xyz2 = (const float*)d_in[1];
    const float* p1   = (const float*)d_in[2];
    const float* p2   = (const float*)d_in[3];
    const float* w1   = (const float*)d_in[4];
    const float* b1   = (const float*)d_in[5];
    const float* w2   = (const float*)d_in[6];
    const float* b2   = (const float*)d_in[7];
    float* out = (float*)d_out;

    // Output = (xyz_2, interpolated + p2) flattened
    cudaMemcpyAsync(out, xyz2, (size_t)BB * 3 * NN * sizeof(float),
                    cudaMemcpyDeviceToDevice);

    knn_part_kernel<<<dim3(NN / 256, CH, BB), 256>>>(xyz1, xyz2);
    knn_merge_kernel<<<(BB * NN) / 256, 256>>>(xyz2);
    // gemm1: 64x128 tile -> 256 CTAs (fills the chip in one light wave)
    gemm_ffma<1, 64><<<dim3(MM / 128, CC / 64, BB), 256>>>(w1, b1, p1, nullptr);
    // gemm2: 128x128 tile
    gemm_ffma<2, 128><<<dim3(NN / 128, CC / 128, BB), 256>>>(
        w2, b2, p2, out + (size_t)BB * 3 * NN);
}

// round 16
// speedup vs baseline: 1.5549x; 1.4307x over previous
#include <cuda_runtime.h>
#include <float.h>
#include <cstdint>

#define BB 2
#define MM 4096
#define NN 16384
#define CC 256
#define KK 3
#define CH 16
#define CHM (MM / CH)   // 256 candidates per chunk

// Scratch (no cudaMalloc allowed)
__device__ float g_p1t[BB * MM * CC];       // p1 transposed: [b][m][o], o contiguous
__device__ int   g_idx[BB * NN * KK];
__device__ float g_wgt[BB * NN * KK];
__device__ float g_pd[BB * NN * CH * KK];
__device__ int   g_pi[BB * NN * CH * KK];

// ---------------------------------------------------------------------------
// kNN partial: 256 queries x one 256-candidate chunk per block.
// Surrogate distance d = |p|^2 - 2 q.p (|q|^2 added in merge).
// ---------------------------------------------------------------------------
__global__ void knn_part_kernel(const float* __restrict__ xyz1,
                                const float* __restrict__ xyz2) {
    __shared__ float4 s[CHM];
    const int b = blockIdx.z;
    const int c = blockIdx.y;
    const int mbase = c * CHM;
    for (int t = threadIdx.x; t < CHM; t += 256) {
        const float x = xyz1[(b * 3 + 0) * MM + mbase + t];
        const float y = xyz1[(b * 3 + 1) * MM + mbase + t];
        const float z = xyz1[(b * 3 + 2) * MM + mbase + t];
        s[t] = make_float4(x, y, z, fmaf(x, x, fmaf(y, y, z * z)));
    }
    __syncthreads();

    const int n = blockIdx.x * 256 + threadIdx.x;
    const float ax = -2.0f * xyz2[(b * 3 + 0) * NN + n];
    const float ay = -2.0f * xyz2[(b * 3 + 1) * NN + n];
    const float az = -2.0f * xyz2[(b * 3 + 2) * NN + n];

    float d0 = FLT_MAX, d1 = FLT_MAX, d2 = FLT_MAX;
    int   i0 = 0, i1 = 0, i2 = 0;

    #pragma unroll 4
    for (int m = 0; m < CHM; m++) {
        const float4 p = s[m];
        const float d = fmaf(p.x, ax, fmaf(p.y, ay, fmaf(p.z, az, p.w)));
        if (d < d2) {
            const int gi = mbase + m;
            if (d < d1) {
                if (d < d0) { d2 = d1; i2 = i1; d1 = d0; i1 = i0; d0 = d; i0 = gi; }
                else        { d2 = d1; i2 = i1; d1 = d;  i1 = gi; }
            } else          { d2 = d;  i2 = gi; }
        }
    }

    const int base = ((b * NN + n) * CH + c) * KK;
    g_pd[base + 0] = d0; g_pd[base + 1] = d1; g_pd[base + 2] = d2;
    g_pi[base + 0] = i0; g_pi[base + 1] = i1; g_pi[base + 2] = i2;
}

// ---------------------------------------------------------------------------
// kNN merge: merge 16 chunk-ordered top-3 partials; compute weights.
// ---------------------------------------------------------------------------
__global__ void knn_merge_kernel(const float* __restrict__ xyz2) {
    const int gid = blockIdx.x * 256 + threadIdx.x;
    const int b = gid / NN;
    const int n = gid - b * NN;

    const float qx = xyz2[(b * 3 + 0) * NN + n];
    const float qy = xyz2[(b * 3 + 1) * NN + n];
    const float qz = xyz2[(b * 3 + 2) * NN + n];
    const float qn = fmaf(qx, qx, fmaf(qy, qy, qz * qz));

    float d0 = FLT_MAX, d1 = FLT_MAX, d2 = FLT_MAX;
    int   i0 = 0, i1 = 0, i2 = 0;
    const int base = gid * CH * KK;
    #pragma unroll
    for (int t = 0; t < CH * KK; t++) {
        const float d = g_pd[base + t];
        if (d < d2) {
            const int gi = g_pi[base + t];
            if (d < d1) {
                if (d < d0) { d2 = d1; i2 = i1; d1 = d0; i1 = i0; d0 = d; i0 = gi; }
                else        { d2 = d1; i2 = i1; d1 = d;  i1 = gi; }
            } else          { d2 = d;  i2 = gi; }
        }
    }

    const float e0 = fmaxf(d0 + qn, 0.0f);
    const float e1 = fmaxf(d1 + qn, 0.0f);
    const float e2 = fmaxf(d2 + qn, 0.0f);
    const float r0 = 1.0f / (e0 + 1e-8f);
    const float r1 = 1.0f / (e1 + 1e-8f);
    const float r2 = 1.0f / (e2 + 1e-8f);
    const float sc = 1.0f / (r0 + r1 + r2);

    const int ob = gid * KK;
    g_idx[ob + 0] = i0; g_idx[ob + 1] = i1; g_idx[ob + 2] = i2;
    g_wgt[ob + 0] = r0 * sc; g_wgt[ob + 1] = r1 * sc; g_wgt[ob + 2] = r2 * sc;
}

// ---------------------------------------------------------------------------
// bf16 split helpers + mma/ldmatrix wrappers
// ---------------------------------------------------------------------------
__device__ __forceinline__ void bf16_split2(float vx, float vy,
                                            uint32_t& hi, uint32_t& lo) {
    uint32_t h;
    asm("cvt.rn.bf16x2.f32 %0, %1, %2;" : "=r"(h) : "f"(vy), "f"(vx));
    const float h0 = __uint_as_float(h << 16);
    const float h1 = __uint_as_float(h & 0xffff0000u);
    const float l0 = vx - h0;
    const float l1 = vy - h1;
    uint32_t l;
    asm("cvt.rn.bf16x2.f32 %0, %1, %2;" : "=r"(l) : "f"(l1), "f"(l0));
    hi = h; lo = l;
}

__device__ __forceinline__ void ldm_x4(uint32_t* r, uint32_t addr) {
    asm volatile("ldmatrix.sync.aligned.m8n8.x4.shared.b16 {%0,%1,%2,%3}, [%4];"
                 : "=r"(r[0]), "=r"(r[1]), "=r"(r[2]), "=r"(r[3]) : "r"(addr));
}
__device__ __forceinline__ void ldm_x4t(uint32_t* r, uint32_t addr) {
    asm volatile("ldmatrix.sync.aligned.m8n8.x4.trans.shared.b16 {%0,%1,%2,%3}, [%4];"
                 : "=r"(r[0]), "=r"(r[1]), "=r"(r[2]), "=r"(r[3]) : "r"(addr));
}
__device__ __forceinline__ void mma_bf16(float* c, const uint32_t* a,
                                         const uint32_t* b) {
    asm volatile(
        "mma.sync.aligned.m16n8k16.row.col.f32.bf16.bf16.f32 "
        "{%0,%1,%2,%3}, {%4,%5,%6,%7}, {%8,%9}, {%0,%1,%2,%3};"
        : "+f"(c[0]), "+f"(c[1]), "+f"(c[2]), "+f"(c[3])
        : "r"(a[0]), "r"(a[1]), "r"(a[2]), "r"(a[3]), "r"(b[0]), "r"(b[1]));
}

// ---------------------------------------------------------------------------
// bf16-split tensor-core GEMM engine. Block tile OT(o) x 128(x), 256 threads.
// 8 warps as 2x4: warp (wr,wc) owns (OT/2 o) x (32 x). K-chunks of 16,
// double-buffered smem of split bf16 tiles:
//   A: [m][k] hi+lo (ldmatrix), B: [k][n] hi+lo (ldmatrix.trans).
// 3 HMMA per tile-kstep: hi*hi + hi*lo + lo*hi (error ~2^-16, ok vs 1e-3).
// WHICH==1: x = m over points_1 -> writes g_p1t[b][m][o] + b1.
// WHICH==2: x = n over points_2 -> writes out[b][o][n] + b2 + 3-NN gather.
// ---------------------------------------------------------------------------
template <int WHICH, int OT>
__global__ __launch_bounds__(256, 2) void gemm_mma(
        const float* __restrict__ W, const float* __restrict__ bias_v,
        const float* __restrict__ P, float* __restrict__ outp) {
    constexpr int MT_W = OT / 32;              // m16 tiles per warp (2 or 4)
    constexpr int NA   = OT / 32;              // A float2 loads per thread
    constexpr int A_BYTES = OT * 32;           // one A matrix (bf16 [m][k16])
    constexpr int SBUF = A_BYTES * 2 + 8192;   // Ahi,Alo + Bhi,Blo(4KB each)
    constexpr int NCH  = CC / 16;

    __shared__ __align__(16) char smem[2 * SBUF];
    const uint32_t sbase = (uint32_t)__cvta_generic_to_shared(smem);

    const int b  = blockIdx.z;
    const int x0 = blockIdx.x * 128;
    const int o0 = blockIdx.y * OT;
    const int tid  = threadIdx.x;
    const int warp = tid >> 5;
    const int lane = tid & 31;
    const int wr = warp >> 2, wc = warp & 3;
    const size_t XDIM = (WHICH == 1) ? MM : NN;

    // ---- loader mappings ----
    // A: id = tid + i*256 -> m = id>>3, kp = id&7 (k-pair)
    int am[NA], akp[NA];
    #pragma unroll
    for (int i = 0; i < NA; i++) {
        const int id = tid + i * 256;
        am[i] = id >> 3; akp[i] = id & 7;
    }
    // B: id = tid + i*256 -> k = id>>6, np = id&63 (n-pair)
    int bk[4], bnp[4];
    #pragma unroll
    for (int i = 0; i < 4; i++) {
        const int id = tid + i * 256;
        bk[i] = id >> 6; bnp[i] = id & 63;
    }

    float2 pa[NA], pb[4];
    #pragma unroll
    for (int i = 0; i < NA; i++)
        pa[i] = *(const float2*)&W[(o0 + am[i]) * CC + akp[i] * 2];
    #pragma unroll
    for (int i = 0; i < 4; i++)
        pb[i] = *(const float2*)&P[((size_t)(b * CC) + bk[i]) * XDIM + x0 + bnp[i] * 2];

    // store helper (to buffer `bf`)
    auto store_chunk = [&](int bf) {
        const uint32_t base = sbase + bf * SBUF;
        #pragma unroll
        for (int i = 0; i < NA; i++) {
            uint32_t hi, lo;
            bf16_split2(pa[i].x, pa[i].y, hi, lo);
            const int m = am[i], kp = akp[i];
            const uint32_t off = m * 32 + (((kp >> 2) ^ ((m >> 2) & 1)) << 4)
                               + (kp & 3) * 4;
            *(uint32_t*)(smem + bf * SBUF + off) = hi;
            *(uint32_t*)(smem + bf * SBUF + A_BYTES + off) = lo;
        }
        #pragma unroll
        for (int i = 0; i < 4; i++) {
            uint32_t hi, lo;
            bf16_split2(pb[i].x, pb[i].y, hi, lo);
            const int k = bk[i], np = bnp[i];
            const uint32_t off = k * 256 + (((np >> 2) ^ (k & 7)) << 4)
                               + (np & 3) * 4;
            *(uint32_t*)(smem + bf * SBUF + 2 * A_BYTES + off) = hi;
            *(uint32_t*)(smem + bf * SBUF + 2 * A_BYTES + 4096 + off) = lo;
        }
        (void)base;
    };

    float acc[MT_W][4][4];
    #pragma unroll
    for (int i = 0; i < MT_W; i++)
        #pragma unroll
        for (int j = 0; j < 4; j++)
            #pragma unroll
            for (int e = 0; e < 4; e++) acc[i][j][e] = 0.0f;

    store_chunk(0);
    __syncthreads();

    // ---- ldmatrix per-lane addresses (offsets within regions) ----
    // A: m_local = wr*(OT/2) + mt*16 + ((lane>>3)&1)*8 + (lane&7); kh = lane>>4
    const int a_mrow = wr * (OT / 2) + ((lane >> 3) & 1) * 8 + (lane & 7);
    const int a_kh   = lane >> 4;
    // B: k_local = ((lane>>3)&1)*8 + (lane&7); ntile = wc*4 + g*2 + (lane>>4)
    const int b_krow = ((lane >> 3) & 1) * 8 + (lane & 7);
    const int b_ntl  = (lane >> 4);

    #pragma unroll 1
    for (int kc = 0; kc < NCH; kc++) {
        const int buf = kc & 1;
        const uint32_t abase = sbase + buf * SBUF;
        const uint32_t bbase = abase + 2 * A_BYTES;

        if (kc + 1 < NCH) {
            const int kb = (kc + 1) * 16;
            #pragma unroll
            for (int i = 0; i < NA; i++)
                pa[i] = *(const float2*)&W[(o0 + am[i]) * CC + kb + akp[i] * 2];
            #pragma unroll
            for (int i = 0; i < 4; i++)
                pb[i] = *(const float2*)&P[((size_t)(b * CC) + kb + bk[i]) * XDIM
                                           + x0 + bnp[i] * 2];
        }

        // B fragments (4 n-tiles x {hi,lo})
        uint32_t bh[4][2], bl[4][2];
        #pragma unroll
        for (int g = 0; g < 2; g++) {
            const int nt = wc * 4 + g * 2 + b_ntl;
            const uint32_t off = b_krow * 256 + ((nt ^ (b_krow & 7)) << 4);
            uint32_t r[4];
            ldm_x4t(r, bbase + off);
            bh[g * 2 + 0][0] = r[0]; bh[g * 2 + 0][1] = r[1];
            bh[g * 2 + 1][0] = r[2]; bh[g * 2 + 1][1] = r[3];
            ldm_x4t(r, bbase + 4096 + off);
            bl[g * 2 + 0][0] = r[0]; bl[g * 2 + 0][1] = r[1];
            bl[g * 2 + 1][0] = r[2]; bl[g * 2 + 1][1] = r[3];
        }

        #pragma unroll
        for (int mt = 0; mt < MT_W; mt++) {
            const int m = a_mrow + mt * 16;
            const uint32_t off = m * 32 + (((a_kh) ^ ((m >> 2) & 1)) << 4);
            uint32_t ah[4], al[4];
            ldm_x4(ah, abase + off);
            ldm_x4(al, abase + A_BYTES + off);
            #pragma unroll
            for (int nt = 0; nt < 4; nt++) {
                mma_bf16(acc[mt][nt], ah, bh[nt]);
                mma_bf16(acc[mt][nt], ah, bl[nt]);
                mma_bf16(acc[mt][nt], al, bh[nt]);
            }
        }

        if (kc + 1 < NCH) {
            store_chunk(buf ^ 1);
            __syncthreads();
        }
    }

    // ---- epilogue ----
    // acc tile (mt,nt): c0:(r, c) c1:(r, c+1) c2:(r+8, c) c3:(r+8, c+1)
    // r = o0 + wr*(OT/2) + mt*16 + (lane>>2); c = x0 + wc*32 + nt*8 + (lane&3)*2
    const int r_base = o0 + wr * (OT / 2) + (lane >> 2);
    const int c_base = x0 + wc * 32 + (lane & 3) * 2;

    if (WHICH == 1) {
        // p1t[b][m][o] = acc + b1[o]
        #pragma unroll
        for (int mt = 0; mt < MT_W; mt++) {
            const int o_r0 = r_base + mt * 16;
            const int o_r1 = o_r0 + 8;
            const float bv0 = bias_v[o_r0];
            const float bv1 = bias_v[o_r1];
            #pragma unroll
            for (int nt = 0; nt < 4; nt++) {
                const int m0 = c_base + nt * 8;
                float* p0 = &g_p1t[((size_t)(b * MM + m0)) * CC];
                float* p1 = &g_p1t[((size_t)(b * MM + m0 + 1)) * CC];
                p0[o_r0] = acc[mt][nt][0] + bv0;
                p1[o_r0] = acc[mt][nt][1] + bv0;
                p0[o_r1] = acc[mt][nt][2] + bv1;
                p1[o_r1] = acc[mt][nt][3] + bv1;
            }
        }
    } else {
        #pragma unroll
        for (int nt = 0; nt < 4; nt++) {
            const int n0 = c_base + nt * 8;
            const int kb0 = (b * NN + n0) * KK;
            const int kb1 = kb0 + KK;
            const int i00 = g_idx[kb0 + 0], i01 = g_idx[kb0 + 1], i02 = g_idx[kb0 + 2];
            const int i10 = g_idx[kb1 + 0], i11 = g_idx[kb1 + 1], i12 = g_idx[kb1 + 2];
            const float w00 = g_wgt[kb0 + 0], w01 = g_wgt[kb0 + 1], w02 = g_wgt[kb0 + 2];
            const float w10 = g_wgt[kb1 + 0], w11 = g_wgt[kb1 + 1], w12 = g_wgt[kb1 + 2];
            const float* q00 = &g_p1t[((size_t)(b * MM + i00)) * CC];
            const float* q01 = &g_p1t[((size_t)(b * MM + i01)) * CC];
            const float* q02 = &g_p1t[((size_t)(b * MM + i02)) * CC];
            const float* q10 = &g_p1t[((size_t)(b * MM + i10)) * CC];
            const float* q11 = &g_p1t[((size_t)(b * MM + i11)) * CC];
            const float* q12 = &g_p1t[((size_t)(b * MM + i12)) * CC];
            #pragma unroll
            for (int mt = 0; mt < MT_W; mt++) {
                const int o_r0 = r_base + mt * 16;
                const int o_r1 = o_r0 + 8;
                const float bv0 = bias_v[o_r0];
                const float bv1 = bias_v[o_r1];
                float2 v0, v1;
                v0.x = acc[mt][nt][0] + bv0
                     + fmaf(w00, q00[o_r0], fmaf(w01, q01[o_r0], w02 * q02[o_r0]));
                v0.y = acc[mt][nt][1] + bv0
                     + fmaf(w10, q10[o_r0], fmaf(w11, q11[o_r0], w12 * q12[o_r0]));
                v1.x = acc[mt][nt][2] + bv1
                     + fmaf(w00, q00[o_r1], fmaf(w01, q01[o_r1], w02 * q02[o_r1]));
                v1.y = acc[mt][nt][3] + bv1
                     + fmaf(w10, q10[o_r1], fmaf(w11, q11[o_r1], w12 * q12[o_r1]));
                *(float2*)&outp[((size_t)(b * CC + o_r0)) * NN + n0] = v0;
                *(float2*)&outp[((size_t)(b * CC + o_r1)) * NN + n0] = v1;
            }
        }
    }
}

extern "C" void kernel_launch(void* const* d_in, const int* in_sizes, int n_in,
                              void* d_out, int out_size) {
    const float* xyz1 = (const float*)d_in[0];
    const float* xyz2 = (const float*)d_in[1];
    const float* p1   = (const float*)d_in[2];
    const float* p2   = (const float*)d_in[3];
    const float* w1   = (const float*)d_in[4];
    const float* b1   = (const float*)d_in[5];
    const float* w2   = (const float*)d_in[6];
    const float* b2   = (const float*)d_in[7];
    float* out = (float*)d_out;

    // Output = (xyz_2, interpolated + p2) flattened
    cudaMemcpyAsync(out, xyz2, (size_t)BB * 3 * NN * sizeof(float),
                    cudaMemcpyDeviceToDevice);

    knn_part_kernel<<<dim3(NN / 256, CH, BB), 256>>>(xyz1, xyz2);
    knn_merge_kernel<<<(BB * NN) / 256, 256>>>(xyz2);
    // gemm1: 64x128 tiles -> 256 CTAs
    gemm_mma<1, 64><<<dim3(MM / 128, CC / 64, BB), 256>>>(w1, b1, p1, nullptr);
    // gemm2: 128x128 tiles -> 512 CTAs
    gemm_mma<2, 128><<<dim3(NN / 128, CC / 128, BB), 256>>>(
        w2, b2, p2, out + (size_t)BB * 3 * NN);
}

// round 17
// speedup vs baseline: 1.5718x; 1.0109x over previous
#include <cuda_runtime.h>
#include <float.h>
#include <cstdint>

#define BB 2
#define MM 4096
#define NN 16384
#define CC 256
#define KK 3
#define CH 16
#define CHM (MM / CH)   // 256 candidates per chunk

// Scratch (no cudaMalloc allowed)
__device__ float g_p1t[BB * MM * CC];          // p1 transposed: [b][m][o]
__device__ int   g_idx[BB * NN * KK];
__device__ float g_wgt[BB * NN * KK];
__device__ float g_pd[BB * NN * CH * KK];
__device__ int   g_pi[BB * NN * CH * KK];
__device__ uint32_t g_wsp[2][2][CC * CC / 2];  // [w1/w2][hi/lo] packed bf16x2

__device__ __forceinline__ void cp_async16(uint32_t dst, const void* src) {
    asm volatile("cp.async.cg.shared.global [%0], [%1], 16;" :: "r"(dst), "l"(src));
}
#define CP_COMMIT() asm volatile("cp.async.commit_group;" ::: "memory")
#define CP_WAIT0()  asm volatile("cp.async.wait_group 0;" ::: "memory")

__device__ __forceinline__ void bf16_split2(float vx, float vy,
                                            uint32_t& hi, uint32_t& lo) {
    uint32_t h;
    asm("cvt.rn.bf16x2.f32 %0, %1, %2;" : "=r"(h) : "f"(vy), "f"(vx));
    const float h0 = __uint_as_float(h << 16);
    const float h1 = __uint_as_float(h & 0xffff0000u);
    const float l0 = vx - h0;
    const float l1 = vy - h1;
    uint32_t l;
    asm("cvt.rn.bf16x2.f32 %0, %1, %2;" : "=r"(l) : "f"(l1), "f"(l0));
    hi = h; lo = l;
}

__device__ __forceinline__ void ldm_x4(uint32_t* r, uint32_t addr) {
    asm volatile("ldmatrix.sync.aligned.m8n8.x4.shared.b16 {%0,%1,%2,%3}, [%4];"
                 : "=r"(r[0]), "=r"(r[1]), "=r"(r[2]), "=r"(r[3]) : "r"(addr));
}
__device__ __forceinline__ void ldm_x4t(uint32_t* r, uint32_t addr) {
    asm volatile("ldmatrix.sync.aligned.m8n8.x4.trans.shared.b16 {%0,%1,%2,%3}, [%4];"
                 : "=r"(r[0]), "=r"(r[1]), "=r"(r[2]), "=r"(r[3]) : "r"(addr));
}
__device__ __forceinline__ void mma_bf16(float* c, const uint32_t* a,
                                         const uint32_t* b) {
    asm volatile(
        "mma.sync.aligned.m16n8k16.row.col.f32.bf16.bf16.f32 "
        "{%0,%1,%2,%3}, {%4,%5,%6,%7}, {%8,%9}, {%0,%1,%2,%3};"
        : "+f"(c[0]), "+f"(c[1]), "+f"(c[2]), "+f"(c[3])
        : "r"(a[0]), "r"(a[1]), "r"(a[2]), "r"(a[3]), "r"(b[0]), "r"(b[1]));
}

// ---------------------------------------------------------------------------
// W pre-split: w1, w2 fp32 -> packed bf16 hi/lo planes in g_wsp.
// ---------------------------------------------------------------------------
__global__ void wsplit_kernel(const float* __restrict__ w1,
                              const float* __restrict__ w2) {
    const int gid = blockIdx.x * 256 + threadIdx.x;   // 0..65535
    const int which = gid >> 15;
    const int e = gid & 32767;
    const float2 v = ((const float2*)(which ? w2 : w1))[e];
    uint32_t hi, lo;
    bf16_split2(v.x, v.y, hi, lo);
    g_wsp[which][0][e] = hi;
    g_wsp[which][1][e] = lo;
}

// ---------------------------------------------------------------------------
// kNN partial: 512 queries (2 per thread) x one 256-candidate chunk.
// Surrogate distance d = |p|^2 - 2 q.p (|q|^2 added in merge).
// ---------------------------------------------------------------------------
__global__ void knn_part_kernel(const float* __restrict__ xyz1,
                                const float* __restrict__ xyz2) {
    __shared__ float4 s[CHM];
    const int b = blockIdx.z;
    const int c = blockIdx.y;
    const int mbase = c * CHM;
    {
        const int t = threadIdx.x;   // CHM == 256
        const float x = xyz1[(b * 3 + 0) * MM + mbase + t];
        const float y = xyz1[(b * 3 + 1) * MM + mbase + t];
        const float z = xyz1[(b * 3 + 2) * MM + mbase + t];
        s[t] = make_float4(x, y, z, fmaf(x, x, fmaf(y, y, z * z)));
    }
    __syncthreads();

    const int nA = blockIdx.x * 512 + threadIdx.x;
    const int nB = nA + 256;
    const float axA = -2.0f * xyz2[(b * 3 + 0) * NN + nA];
    const float ayA = -2.0f * xyz2[(b * 3 + 1) * NN + nA];
    const float azA = -2.0f * xyz2[(b * 3 + 2) * NN + nA];
    const float axB = -2.0f * xyz2[(b * 3 + 0) * NN + nB];
    const float ayB = -2.0f * xyz2[(b * 3 + 1) * NN + nB];
    const float azB = -2.0f * xyz2[(b * 3 + 2) * NN + nB];

    float dA0 = FLT_MAX, dA1 = FLT_MAX, dA2 = FLT_MAX;
    int   iA0 = 0, iA1 = 0, iA2 = 0;
    float dB0 = FLT_MAX, dB1 = FLT_MAX, dB2 = FLT_MAX;
    int   iB0 = 0, iB1 = 0, iB2 = 0;

    #pragma unroll 4
    for (int m = 0; m < CHM; m++) {
        const float4 p = s[m];
        const int gi = mbase + m;
        const float dA = fmaf(p.x, axA, fmaf(p.y, ayA, fmaf(p.z, azA, p.w)));
        if (dA < dA2) {
            if (dA < dA1) {
                if (dA < dA0) { dA2 = dA1; iA2 = iA1; dA1 = dA0; iA1 = iA0; dA0 = dA; iA0 = gi; }
                else          { dA2 = dA1; iA2 = iA1; dA1 = dA;  iA1 = gi; }
            } else            { dA2 = dA;  iA2 = gi; }
        }
        const float dB = fmaf(p.x, axB, fmaf(p.y, ayB, fmaf(p.z, azB, p.w)));
        if (dB < dB2) {
            if (dB < dB1) {
                if (dB < dB0) { dB2 = dB1; iB2 = iB1; dB1 = dB0; iB1 = iB0; dB0 = dB; iB0 = gi; }
                else          { dB2 = dB1; iB2 = iB1; dB1 = dB;  iB1 = gi; }
            } else            { dB2 = dB;  iB2 = gi; }
        }
    }

    const int baseA = ((b * NN + nA) * CH + c) * KK;
    g_pd[baseA + 0] = dA0; g_pd[baseA + 1] = dA1; g_pd[baseA + 2] = dA2;
    g_pi[baseA + 0] = iA0; g_pi[baseA + 1] = iA1; g_pi[baseA + 2] = iA2;
    const int baseB = ((b * NN + nB) * CH + c) * KK;
    g_pd[baseB + 0] = dB0; g_pd[baseB + 1] = dB1; g_pd[baseB + 2] = dB2;
    g_pi[baseB + 0] = iB0; g_pi[baseB + 1] = iB1; g_pi[baseB + 2] = iB2;
}

// ---------------------------------------------------------------------------
// kNN merge: merge 16 chunk-ordered top-3 partials; compute weights.
// ---------------------------------------------------------------------------
__global__ void knn_merge_kernel(const float* __restrict__ xyz2) {
    const int gid = blockIdx.x * 256 + threadIdx.x;
    const int b = gid / NN;
    const int n = gid - b * NN;

    const float qx = xyz2[(b * 3 + 0) * NN + n];
    const float qy = xyz2[(b * 3 + 1) * NN + n];
    const float qz = xyz2[(b * 3 + 2) * NN + n];
    const float qn = fmaf(qx, qx, fmaf(qy, qy, qz * qz));

    float d0 = FLT_MAX, d1 = FLT_MAX, d2 = FLT_MAX;
    int   i0 = 0, i1 = 0, i2 = 0;
    const int base = gid * CH * KK;
    #pragma unroll
    for (int t = 0; t < CH * KK; t++) {
        const float d = g_pd[base + t];
        if (d < d2) {
            const int gi = g_pi[base + t];
            if (d < d1) {
                if (d < d0) { d2 = d1; i2 = i1; d1 = d0; i1 = i0; d0 = d; i0 = gi; }
                else        { d2 = d1; i2 = i1; d1 = d;  i1 = gi; }
            } else          { d2 = d;  i2 = gi; }
        }
    }

    const float e0 = fmaxf(d0 + qn, 0.0f);
    const float e1 = fmaxf(d1 + qn, 0.0f);
    const float e2 = fmaxf(d2 + qn, 0.0f);
    const float r0 = 1.0f / (e0 + 1e-8f);
    const float r1 = 1.0f / (e1 + 1e-8f);
    const float r2 = 1.0f / (e2 + 1e-8f);
    const float sc = 1.0f / (r0 + r1 + r2);

    const int ob = gid * KK;
    g_idx[ob + 0] = i0; g_idx[ob + 1] = i1; g_idx[ob + 2] = i2;
    g_wgt[ob + 0] = r0 * sc; g_wgt[ob + 1] = r1 * sc; g_wgt[ob + 2] = r2 * sc;
}

// ---------------------------------------------------------------------------
// bf16-split tensor-core GEMM. Block tile OT(o) x 128(x), 256 threads,
// warps 2x4. A = pre-split W (cp.async from g_wsp[WSEL], zero mainloop math);
// B = fp32 points, split in-kernel (float4 loads, STS.64). Double-buffered,
// 3 HMMA per tile-kstep (hi*hi + hi*lo + lo*hi).
// WHICH==1: x = m over points_1 -> g_p1t[b][m][o] + b1.
// WHICH==2: x = n over points_2 -> out[b][o][n] + b2 + 3-NN gather.
// ---------------------------------------------------------------------------
template <int WHICH, int OT, int WSEL>
__global__ __launch_bounds__(256, 2) void gemm_mma(
        const float* __restrict__ bias_v,
        const float* __restrict__ P, float* __restrict__ outp) {
    constexpr int MT_W = OT / 32;              // m16 tiles per warp
    constexpr int A_BYTES = OT * 32;           // one A plane (bf16 [m][k16])
    constexpr int SBUF = A_BYTES * 2 + 8192;   // Ahi,Alo + Bhi,Blo(4KB each)
    constexpr int NCH  = CC / 16;
    constexpr int NIT_A = (4 * OT) / 256;      // A cp.async per thread (1 or 2)

    __shared__ __align__(16) char smem[2 * SBUF];
    const uint32_t sbase = (uint32_t)__cvta_generic_to_shared(smem);

    const int b  = blockIdx.z;
    const int x0 = blockIdx.x * 128;
    const int o0 = blockIdx.y * OT;
    const int tid  = threadIdx.x;
    const int warp = tid >> 5;
    const int lane = tid & 31;
    const int wr = warp >> 2, wc = warp & 3;
    const size_t XDIM = (WHICH == 1) ? MM : NN;

    // ---- A cp.async mapping: 16B block = (plane, m, kh) ----
    int a_pl[NIT_A], a_m[NIT_A], a_kh[NIT_A];
    uint32_t a_dst[NIT_A];
    #pragma unroll
    for (int i = 0; i < NIT_A; i++) {
        const int id = tid + i * 256;
        a_pl[i] = id / (2 * OT);
        const int r = id % (2 * OT);
        a_m[i]  = r >> 1;
        a_kh[i] = r & 1;
        a_dst[i] = (uint32_t)(a_pl[i] * A_BYTES + a_m[i] * 32
                 + ((a_kh[i] ^ ((a_m[i] >> 2) & 1)) << 4));
    }
    // ---- B mapping: 2 float4 per thread per chunk ----
    int bkk[2], bnq[2];
    #pragma unroll
    for (int i = 0; i < 2; i++) {
        const int id = tid + i * 256;
        bkk[i] = id >> 5;          // k 0..15
        bnq[i] = id & 31;          // n-quad 0..31
    }

    auto a_src = [&](int kb, int i) -> const char* {
        return (const char*)g_wsp[WSEL][a_pl[i]]
             + ((size_t)(o0 + a_m[i]) * CC + kb + a_kh[i] * 8) * 2;
    };

    float4 pb[2];
    #pragma unroll
    for (int i = 0; i < 2; i++)
        pb[i] = *(const float4*)&P[((size_t)(b * CC) + bkk[i]) * XDIM + x0 + bnq[i] * 4];

    auto store_B = [&](int bf) {
        #pragma unroll
        for (int i = 0; i < 2; i++) {
            uint32_t h0, l0, h1, l1;
            bf16_split2(pb[i].x, pb[i].y, h0, l0);
            bf16_split2(pb[i].z, pb[i].w, h1, l1);
            const int k = bkk[i], nq = bnq[i];
            const uint32_t off = bf * SBUF + 2 * A_BYTES + k * 256
                               + (((nq >> 1) ^ (k & 7)) << 4) + (nq & 1) * 8;
            *(uint2*)(smem + off) = make_uint2(h0, h1);
            *(uint2*)(smem + off + 4096) = make_uint2(l0, l1);
        }
    };

    // ---- prologue: chunk 0 ----
    #pragma unroll
    for (int i = 0; i < NIT_A; i++)
        cp_async16(sbase + a_dst[i], a_src(0, i));
    CP_COMMIT();
    store_B(0);
    CP_WAIT0();
    __syncthreads();

    float acc[MT_W][4][4];
    #pragma unroll
    for (int i = 0; i < MT_W; i++)
        #pragma unroll
        for (int j = 0; j < 4; j++)
            #pragma unroll
            for (int e = 0; e < 4; e++) acc[i][j][e] = 0.0f;

    // ldmatrix per-lane rows
    const int lm_mrow = wr * (OT / 2) + ((lane >> 3) & 1) * 8 + (lane & 7);
    const int lm_kh   = lane >> 4;
    const int lb_krow = ((lane >> 3) & 1) * 8 + (lane & 7);
    const int lb_ntl  = (lane >> 4);

    #pragma unroll 1
    for (int kc = 0; kc < NCH; kc++) {
        const int buf = kc & 1;
        const uint32_t abase = sbase + buf * SBUF;
        const uint32_t bbase = abase + 2 * A_BYTES;

        if (kc + 1 < NCH) {
            const int kb = (kc + 1) * 16;
            #pragma unroll
            for (int i = 0; i < NIT_A; i++)
                cp_async16(sbase + (buf ^ 1) * SBUF + a_dst[i], a_src(kb, i));
            CP_COMMIT();
            #pragma unroll
            for (int i = 0; i < 2; i++)
                pb[i] = *(const float4*)&P[((size_t)(b * CC) + kb + bkk[i]) * XDIM
                                           + x0 + bnq[i] * 4];
        }

        uint32_t bh[4][2], bl[4][2];
        #pragma unroll
        for (int g = 0; g < 2; g++) {
            const int nt = wc * 4 + g * 2 + lb_ntl;
            const uint32_t off = lb_krow * 256 + ((nt ^ (lb_krow & 7)) << 4);
            uint32_t r[4];
            ldm_x4t(r, bbase + off);
            bh[g * 2 + 0][0] = r[0]; bh[g * 2 + 0][1] = r[1];
            bh[g * 2 + 1][0] = r[2]; bh[g * 2 + 1][1] = r[3];
            ldm_x4t(r, bbase + 4096 + off);
            bl[g * 2 + 0][0] = r[0]; bl[g * 2 + 0][1] = r[1];
            bl[g * 2 + 1][0] = r[2]; bl[g * 2 + 1][1] = r[3];
        }

        #pragma unroll
        for (int mt = 0; mt < MT_W; mt++) {
            const int m = lm_mrow + mt * 16;
            const uint32_t off = m * 32 + ((lm_kh ^ ((m >> 2) & 1)) << 4);
            uint32_t ah[4], al[4];
            ldm_x4(ah, abase + off);
            ldm_x4(al, abase + A_BYTES + off);
            #pragma unroll
            for (int nt = 0; nt < 4; nt++) {
                mma_bf16(acc[mt][nt], ah, bh[nt]);
                mma_bf16(acc[mt][nt], ah, bl[nt]);
                mma_bf16(acc[mt][nt], al, bh[nt]);
            }
        }

        if (kc + 1 < NCH) {
            store_B(buf ^ 1);
            CP_WAIT0();
            __syncthreads();
        }
    }

    // ---- epilogue ----
    const int r_base = o0 + wr * (OT / 2) + (lane >> 2);
    const int c_base = x0 + wc * 32 + (lane & 3) * 2;

    if (WHICH == 1) {
        #pragma unroll
        for (int mt = 0; mt < MT_W; mt++) {
            const int o_r0 = r_base + mt * 16;
            const int o_r1 = o_r0 + 8;
            const float bv0 = bias_v[o_r0];
            const float bv1 = bias_v[o_r1];
            #pragma unroll
            for (int nt = 0; nt < 4; nt++) {
                const int m0 = c_base + nt * 8;
                float* p0 = &g_p1t[((size_t)(b * MM + m0)) * CC];
                float* p1 = &g_p1t[((size_t)(b * MM + m0 + 1)) * CC];
                p0[o_r0] = acc[mt][nt][0] + bv0;
                p1[o_r0] = acc[mt][nt][1] + bv0;
                p0[o_r1] = acc[mt][nt][2] + bv1;
                p1[o_r1] = acc[mt][nt][3] + bv1;
            }
        }
    } else {
        #pragma unroll
        for (int nt = 0; nt < 4; nt++) {
            const int n0 = c_base + nt * 8;
            const int kb0 = (b * NN + n0) * KK;
            const int kb1 = kb0 + KK;
            const int i00 = g_idx[kb0 + 0], i01 = g_idx[kb0 + 1], i02 = g_idx[kb0 + 2];
            const int i10 = g_idx[kb1 + 0], i11 = g_idx[kb1 + 1], i12 = g_idx[kb1 + 2];
            const float w00 = g_wgt[kb0 + 0], w01 = g_wgt[kb0 + 1], w02 = g_wgt[kb0 + 2];
            const float w10 = g_wgt[kb1 + 0], w11 = g_wgt[kb1 + 1], w12 = g_wgt[kb1 + 2];
            const float* q00 = &g_p1t[((size_t)(b * MM + i00)) * CC];
            const float* q01 = &g_p1t[((size_t)(b * MM + i01)) * CC];
            const float* q02 = &g_p1t[((size_t)(b * MM + i02)) * CC];
            const float* q10 = &g_p1t[((size_t)(b * MM + i10)) * CC];
            const float* q11 = &g_p1t[((size_t)(b * MM + i11)) * CC];
            const float* q12 = &g_p1t[((size_t)(b * MM + i12)) * CC];
            #pragma unroll
            for (int mt = 0; mt < MT_W; mt++) {
                const int o_r0 = r_base + mt * 16;
                const int o_r1 = o_r0 + 8;
                const float bv0 = bias_v[o_r0];
                const float bv1 = bias_v[o_r1];
                float2 v0, v1;
                v0.x = acc[mt][nt][0] + bv0
                     + fmaf(w00, q00[o_r0], fmaf(w01, q01[o_r0], w02 * q02[o_r0]));
                v0.y = acc[mt][nt][1] + bv0
                     + fmaf(w10, q10[o_r0], fmaf(w11, q11[o_r0], w12 * q12[o_r0]));
                v1.x = acc[mt][nt][2] + bv1
                     + fmaf(w00, q00[o_r1], fmaf(w01, q01[o_r1], w02 * q02[o_r1]));
                v1.y = acc[mt][nt][3] + bv1
                     + fmaf(w10, q10[o_r1], fmaf(w11, q11[o_r1], w12 * q12[o_r1]));
                *(float2*)&outp[((size_t)(b * CC + o_r0)) * NN + n0] = v0;
                *(float2*)&outp[((size_t)(b * CC + o_r1)) * NN + n0] = v1;
            }
        }
    }
}

extern "C" void kernel_launch(void* const* d_in, const int* in_sizes, int n_in,
                              void* d_out, int out_size) {
    const float* xyz1 = (const float*)d_in[0];
    const float* xyz2 = (const float*)d_in[1];
    const float* p1   = (const float*)d_in[2];
    const float* p2   = (const float*)d_in[3];
    const float* w1   = (const float*)d_in[4];
    const float* b1   = (const float*)d_in[5];
    const float* w2   = (const float*)d_in[6];
    const float* b2   = (const float*)d_in[7];
    float* out = (float*)d_out;

    // Output = (xyz_2, interpolated + p2) flattened
    cudaMemcpyAsync(out, xyz2, (size_t)BB * 3 * NN * sizeof(float),
                    cudaMemcpyDeviceToDevice);

    wsplit_kernel<<<256, 256>>>(w1, w2);
    knn_part_kernel<<<dim3(NN / 512, CH, BB), 256>>>(xyz1, xyz2);
    knn_merge_kernel<<<(BB * NN) / 256, 256>>>(xyz2);
    // gemm1: 64x128 tiles -> 256 CTAs
    gemm_mma<1, 64, 0><<<dim3(MM / 128, CC / 64, BB), 256>>>(b1, p1, nullptr);
    // gemm2: 128x128 tiles -> 512 CTAs
    gemm_mma<2, 128, 1><<<dim3(NN / 128, CC / 128, BB), 256>>>(
        b2, p2, out + (size_t)BB * 3 * NN);
}